// round 7
// baseline (speedup 1.0000x reference)
#include <cuda_runtime.h>
#include <math.h>

// SBEceLoss: logits [N,100] f32, labels [N] i64 -> scalar ece (f32)
// Single fused kernel: warp-per-row, 8 rows/iter.
//   - packed-key REDUX: one __reduce_max_sync gives max value + first-occurrence argmax
//   - guarantee test amortized to ONE ballot per 8 rows via aggregates
//   - per-block shared histogram -> global REDs
//   - last block computes 100x15 bin softmax + ECE, resets device state.

#define C_CLASSES 100
#define NB 15
#define RPI 8
#define FULLM 0xffffffffu
#define REALM 0x01ffffffu   // lanes 0..24 (distinct elements only)

__device__ int g_cnt[C_CLASSES];
__device__ int g_acc[C_CLASSES];
__device__ unsigned g_done;

// Order-preserving float->uint encoding (and inverse).
__device__ __forceinline__ unsigned fenc(float f) {
    unsigned u = __float_as_uint(f);
    return u ^ ((unsigned)((int)u >> 31) | 0x80000000u);
}
__device__ __forceinline__ float fdec(unsigned e) {
    unsigned mask = (~(unsigned)((int)e >> 31)) | 0x80000000u;
    return __uint_as_float(e ^ mask);
}

__global__ void __launch_bounds__(256, 5)
fused_kernel(const float* __restrict__ logits,
             const long long* __restrict__ labels,
             int n_rows, float* __restrict__ out) {
    __shared__ int  s_cnt[C_CLASSES];
    __shared__ int  s_acc[C_CLASSES];
    __shared__ bool s_last;
    for (int i = threadIdx.x; i < C_CLASSES; i += blockDim.x) { s_cnt[i] = 0; s_acc[i] = 0; }
    __syncthreads();

    const int lane  = threadIdx.x & 31;
    const int gw    = blockIdx.x * (blockDim.x >> 5) + (threadIdx.x >> 5);
    const int warps = gridDim.x * (blockDim.x >> 5);
    const float NEG = __int_as_float(0xff800000);

    // lanes 25..31 mirror lanes 0..6 (same 128B sectors -> L1 hits). Their keys
    // duplicate lanes 0..6 exactly, so REDUX results are unaffected.
    const int c4 = (lane < 25) ? lane : (lane - 25);

    const int rows_per_sweep = warps * RPI;
    const int sweeps = n_rows / rows_per_sweep;      // exact for N=2^19
    const int main_rows = sweeps * rows_per_sweep;

    // certify-all-rows constants (127-ulp slack for packed-key masking)
    const unsigned KEY_HI = fenc(8.0f)   - 127u;  // k1 < KEY_HI  => mg < 8
    const unsigned KEY_LO = fenc(-16.0f) + 127u;  // k1 > KEY_LO  => mg > -16

    const float4* p = reinterpret_cast<const float4*>(logits) + (size_t)gw * RPI * 25 + c4;
    int rowbase = gw * RPI;

    for (int s = 0; s < sweeps; ++s) {
        float4 v[RPI];
        #pragma unroll
        for (int r = 0; r < RPI; r++) v[r] = __ldg(p + r * 25);   // MLP=8

        int      my_widx = 0;          // lane r holds row r's winning class
        float    m_min   = __int_as_float(0x7f800000);  // +inf
        unsigned k1_max  = 0u, k1_min = FULLM;

        #pragma unroll
        for (int r = 0; r < RPI; r++) {
            // lane max (fma pipe) + first-occurrence local index
            float m = fmaxf(fmaxf(v[r].x, v[r].y), fmaxf(v[r].z, v[r].w));
            int j = c4 * 4 + ((m == v[r].x) ? 0 : ((m == v[r].y) ? 1 : ((m == v[r].z) ? 2 : 3)));

            // packed key: value (ulp-masked) | inverted index for low-idx tie-break
            unsigned key = (fenc(m) & ~127u) + (127u - (unsigned)j);
            unsigned k1  = __reduce_max_sync(FULLM, key);

            int widx = 127 - (int)(k1 & 127u);
            my_widx  = (lane == r) ? widx : my_widx;

            m_min  = fminf(m_min, m);
            k1_max = max(k1_max, k1);
            k1_min = min(k1_min, k1);
        }

        // one vote certifies all 8 rows:
        //   >=2 DISTINCT lanes whose min-over-rows lane-max > -4, and every
        //   row max in (-16, 8)  =>  per row: 2nd element > -4 >= mg-12 and
        //   |mg| < 16  =>  log(sumexp) >= 6.1e-6 > ulp(8)/2  =>  max logprob
        //   strictly < 0  =>  never equals an integer label => acc=0 for all.
        unsigned bal = __ballot_sync(FULLM, m_min > -4.0f) & REALM;
        bool all_good = (__popc(bal) >= 2) && (k1_max < KEY_HI) && (k1_min > KEY_LO);

        unsigned acc_mask = 0;
        if (!all_good) {   // rare exact path, per-row
            #pragma unroll
            for (int r = 0; r < RPI; r++) {
                float m = fmaxf(fmaxf(v[r].x, v[r].y), fmaxf(v[r].z, v[r].w));
                unsigned k1e = __reduce_max_sync(FULLM, fenc(m));
                float mg = fdec(k1e);
                unsigned b = __ballot_sync(FULLM, m > (mg - 12.0f)) & REALM;
                if ((__popc(b) >= 2) && (fabsf(mg) < 16.0f)) continue;  // acc=0 proven
                float sv = 0.0f;
                if (lane < 25)
                    sv = expf(v[r].x - mg) + expf(v[r].y - mg) +
                         expf(v[r].z - mg) + expf(v[r].w - mg);
                #pragma unroll
                for (int off = 16; off; off >>= 1)
                    sv += __shfl_xor_sync(FULLM, sv, off);
                float pred = mg - (mg + logf(sv));
                if (pred == (float)labels[rowbase + r]) acc_mask |= (1u << r);
            }
        }

        // lane r commits row r (one divergent section per 8 rows)
        if (lane < RPI) {
            atomicAdd(&s_cnt[my_widx], 1);
            if ((acc_mask >> lane) & 1u) atomicAdd(&s_acc[my_widx], 1);
        }

        p += (size_t)warps * RPI * 25;
        rowbase += rows_per_sweep;
    }

    // ---- generic tail (empty for N=2^19 with this launch config) ----
    for (int row = main_rows + gw; row < n_rows; row += warps) {
        float4 vr = (lane < 25)
            ? __ldg(reinterpret_cast<const float4*>(logits + (size_t)row * C_CLASSES) + lane)
            : make_float4(NEG, NEG, NEG, NEG);
        float m = fmaxf(fmaxf(vr.x, vr.y), fmaxf(vr.z, vr.w));
        int j = c4 * 4 + ((m == vr.x) ? 0 : ((m == vr.y) ? 1 : ((m == vr.z) ? 2 : 3)));
        unsigned key = (lane < 25) ? ((fenc(m) & ~127u) + (127u - (unsigned)j)) : 0u;
        unsigned k1  = __reduce_max_sync(FULLM, key);
        bool iswin = (key == k1) && (lane < 25) &&
                     ((__ballot_sync(FULLM, key == k1) & ((1u << lane) - 1u)) == 0);
        float mg = fdec(k1 | 127u);  // within 127 ulp; only used for filter/fallback
        unsigned b = __ballot_sync(FULLM, m > (mg - 11.0f)) & REALM;
        int acc = 0;
        if (!((__popc(b) >= 2) && (fabsf(mg) < 15.0f))) {
            unsigned k1e = __reduce_max_sync(FULLM, lane < 25 ? fenc(m) : 0u);
            float mge = fdec(k1e);
            float sv = 0.0f;
            if (lane < 25)
                sv = expf(vr.x - mge) + expf(vr.y - mge) + expf(vr.z - mge) + expf(vr.w - mge);
            #pragma unroll
            for (int off = 16; off; off >>= 1) sv += __shfl_xor_sync(FULLM, sv, off);
            float pred = mge - (mge + logf(sv));
            acc = (pred == (float)labels[row]) ? 1 : 0;
        }
        if (iswin) {
            int widx = 127 - (int)(k1 & 127u);
            atomicAdd(&s_cnt[widx], 1);
            if (acc) atomicAdd(&s_acc[widx], 1);
        }
    }

    // ---- flush block histogram to global ----
    __syncthreads();
    for (int i = threadIdx.x; i < C_CLASSES; i += blockDim.x) {
        int c = s_cnt[i]; if (c) atomicAdd(&g_cnt[i], c);
        int a = s_acc[i]; if (a) atomicAdd(&g_acc[i], a);
    }
    __threadfence();
    __syncthreads();

    if (threadIdx.x == 0) {
        unsigned rank = atomicAdd(&g_done, 1u);
        s_last = (rank == gridDim.x - 1);
    }
    __syncthreads();
    if (!s_last) return;

    // ================= finalize (last block only) =================
    __shared__ float s_coef[C_CLASSES][NB + 1];
    __shared__ int   s_c2[C_CLASSES];
    __shared__ int   s_a2[C_CLASSES];
    __shared__ float s_sum[NB], s_conf[NB], s_accs[NB];

    int t = threadIdx.x;
    if (t < C_CLASSES) {
        int cnt = __ldcg(&g_cnt[t]);
        int ac  = __ldcg(&g_acc[t]);
        s_c2[t] = cnt;
        s_a2[t] = ac;
        float cf = (float)t;
        float d[NB];
        float dmax = __int_as_float(0xff800000);
        #pragma unroll
        for (int jj = 0; jj < NB; jj++) {
            float aj = (float)((2 * jj + 1) / 30.0);
            float tt = cf - aj;
            d[jj] = -(tt * tt) / 0.01f;
            dmax = fmaxf(dmax, d[jj]);
        }
        float denom = 0.0f;
        #pragma unroll
        for (int jj = 0; jj < NB; jj++) denom += expf(d[jj] - dmax);
        #pragma unroll
        for (int jj = 0; jj < NB; jj++) s_coef[t][jj] = expf(d[jj] - dmax) / denom;
        g_cnt[t] = 0;     // reset for next graph replay
        g_acc[t] = 0;
    }
    if (t == 0) g_done = 0;
    __syncthreads();

    if (t < NB) {
        float sum_c = 0.0f, sum_cc = 0.0f, sum_a = 0.0f;
        for (int c = 0; c < C_CLASSES; c++) {
            int cnt = s_c2[c];
            int ac  = s_a2[c];
            if ((cnt | ac) == 0) continue;
            float coeff = s_coef[c][t];
            float fcnt  = (float)cnt;   // exact: cnt < 2^24
            float cf    = (float)c;
            sum_c  += fcnt * coeff;
            sum_cc += fcnt * cf * coeff;
            sum_a  += (float)ac * coeff;
        }
        s_sum[t]  = sum_c;
        s_conf[t] = sum_cc;
        s_accs[t] = sum_a;
    }
    __syncthreads();

    if (t == 0) {
        float tot = 0.0f;
        #pragma unroll
        for (int jj = 0; jj < NB; jj++) tot += fabsf(s_sum[jj]);
        float wden = fmaxf(tot, 1e-5f);
        float acc2 = 0.0f;
        #pragma unroll
        for (int jj = 0; jj < NB; jj++) {
            float den = fmaxf(s_sum[jj], 1e-5f);
            float bc  = s_conf[jj] / den;
            float ba  = s_accs[jj] / den;
            float w   = s_sum[jj] / wden;
            float df  = bc - ba;
            acc2 += df * df * w;
        }
        out[0] = sqrtf(acc2);
    }
}

extern "C" void kernel_launch(void* const* d_in, const int* in_sizes, int n_in,
                              void* d_out, int out_size) {
    const float*     logits = (const float*)d_in[0];
    const long long* labels = (const long long*)d_in[1];
    float*           out    = (float*)d_out;
    int n_rows = in_sizes[1];  // labels count = N

    // 2048 blocks * 8 warps * 8 rows = 131072 rows/sweep; 2^19/2^17 = 4 exact sweeps
    fused_kernel<<<2048, 256>>>(logits, labels, n_rows, out);
}

// round 8
// speedup vs baseline: 1.4980x; 1.4980x over previous
#include <cuda_runtime.h>
#include <math.h>

// SBEceLoss: logits [N,100] f32, labels [N] i64 -> scalar ece (f32)
// Single fused kernel: warp-per-row, 4 rows/iter (no spills, high occupancy).
//   - exact REDUX argmax (fenc) + ballot/ffs/shfl winner broadcast
//   - certification (acc==0 proof) batched: 1 ballot per 4 rows
//   - per-block shared histogram -> global REDs
//   - last block computes 100x15 bin softmax + ECE, resets device state.

#define C_CLASSES 100
#define NB 15
#define RPI 4
#define FULLM 0xffffffffu
#define REALM 0x01ffffffu   // lanes 0..24 (distinct columns only)

__device__ int g_cnt[C_CLASSES];
__device__ int g_acc[C_CLASSES];
__device__ unsigned g_done;

// Order-preserving float->uint encoding (and inverse).
__device__ __forceinline__ unsigned fenc(float f) {
    unsigned u = __float_as_uint(f);
    return u ^ ((unsigned)((int)u >> 31) | 0x80000000u);
}
__device__ __forceinline__ float fdec(unsigned e) {
    unsigned mask = (~(unsigned)((int)e >> 31)) | 0x80000000u;
    return __uint_as_float(e ^ mask);
}

__global__ void __launch_bounds__(256)
fused_kernel(const float* __restrict__ logits,
             const long long* __restrict__ labels,
             int n_rows, float* __restrict__ out) {
    __shared__ int  s_cnt[C_CLASSES];
    __shared__ int  s_acc[C_CLASSES];
    __shared__ bool s_last;
    for (int i = threadIdx.x; i < C_CLASSES; i += blockDim.x) { s_cnt[i] = 0; s_acc[i] = 0; }
    __syncthreads();

    const int lane  = threadIdx.x & 31;
    const int gw    = blockIdx.x * (blockDim.x >> 5) + (threadIdx.x >> 5);
    const int warps = gridDim.x * (blockDim.x >> 5);
    const float NEG = __int_as_float(0xff800000);

    // lanes 25..31 mirror lanes 0..6: identical addresses -> merged in the same
    // L1 wavefront (zero extra traffic); identical keys -> REDUX unaffected;
    // REALM masks them out of distinct-element counts.
    const int c4 = (lane < 25) ? lane : (lane - 25);

    const int rows_per_sweep = warps * RPI;
    const int sweeps = n_rows / rows_per_sweep;      // 8 exact for N=2^19
    const int main_rows = sweeps * rows_per_sweep;

    const unsigned KEY_HI = fenc(8.0f);    // k1 <  KEY_HI => mg <  8
    const unsigned KEY_LO = fenc(-16.0f);  // k1 >  KEY_LO => mg > -16

    const float4* p = reinterpret_cast<const float4*>(logits) + (size_t)gw * RPI * 25 + c4;
    int rowbase = gw * RPI;

    for (int s = 0; s < sweeps; ++s) {
        float4 v[RPI];
        #pragma unroll
        for (int r = 0; r < RPI; r++) v[r] = __ldg(p + r * 25);   // MLP=4/warp

        int      my_widx = 0;                            // lane r holds row r's class
        float    m_min   = __int_as_float(0x7f800000);   // +inf
        unsigned k1_max  = 0u, k1_min = FULLM;
        unsigned mg_bits[RPI];                           // exact row max (for fallback)

        #pragma unroll
        for (int r = 0; r < RPI; r++) {
            // lane max (fma pipe) + first-occurrence local index
            float m = fmaxf(fmaxf(v[r].x, v[r].y), fmaxf(v[r].z, v[r].w));
            int j = c4 * 4 + ((m == v[r].x) ? 0 : ((m == v[r].y) ? 1 : ((m == v[r].z) ? 2 : 3)));

            unsigned em = fenc(m);                        // exact
            unsigned k1 = __reduce_max_sync(FULLM, em);
            unsigned bal = __ballot_sync(FULLM, em == k1);
            int winner_lane = __ffs(bal) - 1;             // lowest lane = first occurrence
            int widx = __shfl_sync(FULLM, j, winner_lane);
            my_widx = (lane == r) ? widx : my_widx;
            mg_bits[r] = k1;

            m_min  = fminf(m_min, m);
            k1_max = max(k1_max, k1);
            k1_min = min(k1_min, k1);
        }

        // One vote certifies all 4 rows (exact, no ulp slop):
        //   >=2 DISTINCT lanes with min-over-rows lane-max > -4, and every row
        //   max in (-16, 8)  =>  per row: a 2nd element > -4 > mg-12 and
        //   |mg| < 16  =>  log(sumexp) >= log(1+e^-12) = 6.1e-6 > ulp(8)/2
        //   =>  max logprob strictly < 0  =>  never equals an integer label.
        unsigned bal = __ballot_sync(FULLM, m_min > -4.0f) & REALM;
        bool all_good = (__popc(bal) >= 2) && (k1_max < KEY_HI) && (k1_min > KEY_LO);

        unsigned acc_mask = 0;
        if (!all_good) {   // rare exact path
            #pragma unroll
            for (int r = 0; r < RPI; r++) {
                float m  = fmaxf(fmaxf(v[r].x, v[r].y), fmaxf(v[r].z, v[r].w));
                float mg = fdec(mg_bits[r]);
                unsigned b = __ballot_sync(FULLM, m > (mg - 12.0f)) & REALM;
                if ((__popc(b) >= 2) && (fabsf(mg) < 16.0f)) continue;  // acc=0 proven
                float sv = 0.0f;
                if (lane < 25)
                    sv = expf(v[r].x - mg) + expf(v[r].y - mg) +
                         expf(v[r].z - mg) + expf(v[r].w - mg);
                #pragma unroll
                for (int off = 16; off; off >>= 1)
                    sv += __shfl_xor_sync(FULLM, sv, off);
                float pred = mg - (mg + logf(sv));
                if (pred == (float)labels[rowbase + r]) acc_mask |= (1u << r);
            }
        }

        // lane r commits row r (one divergent section per 4 rows)
        if (lane < RPI) {
            atomicAdd(&s_cnt[my_widx], 1);
            if ((acc_mask >> lane) & 1u) atomicAdd(&s_acc[my_widx], 1);
        }

        p += (size_t)warps * RPI * 25;
        rowbase += rows_per_sweep;
    }

    // ---- generic tail (empty for N=2^19 with this launch config) ----
    for (int row = main_rows + gw; row < n_rows; row += warps) {
        float4 vr = (lane < 25)
            ? __ldg(reinterpret_cast<const float4*>(logits + (size_t)row * C_CLASSES) + lane)
            : make_float4(NEG, NEG, NEG, NEG);
        float m = fmaxf(fmaxf(vr.x, vr.y), fmaxf(vr.z, vr.w));
        int j = c4 * 4 + ((m == vr.x) ? 0 : ((m == vr.y) ? 1 : ((m == vr.z) ? 2 : 3)));
        unsigned em = fenc(m);
        unsigned k1 = __reduce_max_sync(FULLM, em);
        unsigned bal = __ballot_sync(FULLM, em == k1);
        bool iswin = (em == k1) && (lane < 25) &&
                     ((bal & ((1u << lane) - 1u)) == 0);
        float mg = fdec(k1);
        unsigned b = __ballot_sync(FULLM, m > (mg - 12.0f)) & REALM;
        int acc = 0;
        if (!((__popc(b) >= 2) && (fabsf(mg) < 16.0f))) {
            float sv = 0.0f;
            if (lane < 25)
                sv = expf(vr.x - mg) + expf(vr.y - mg) + expf(vr.z - mg) + expf(vr.w - mg);
            #pragma unroll
            for (int off = 16; off; off >>= 1) sv += __shfl_xor_sync(FULLM, sv, off);
            float pred = mg - (mg + logf(sv));
            acc = (pred == (float)labels[row]) ? 1 : 0;
        }
        if (iswin) {
            atomicAdd(&s_cnt[j], 1);
            if (acc) atomicAdd(&s_acc[j], 1);
        }
    }

    // ---- flush block histogram to global ----
    __syncthreads();
    for (int i = threadIdx.x; i < C_CLASSES; i += blockDim.x) {
        int c = s_cnt[i]; if (c) atomicAdd(&g_cnt[i], c);
        int a = s_acc[i]; if (a) atomicAdd(&g_acc[i], a);
    }
    __threadfence();
    __syncthreads();

    if (threadIdx.x == 0) {
        unsigned rank = atomicAdd(&g_done, 1u);
        s_last = (rank == gridDim.x - 1);
    }
    __syncthreads();
    if (!s_last) return;

    // ================= finalize (last block only) =================
    __shared__ float s_coef[C_CLASSES][NB + 1];
    __shared__ int   s_c2[C_CLASSES];
    __shared__ int   s_a2[C_CLASSES];
    __shared__ float s_sum[NB], s_conf[NB], s_accs[NB];

    int t = threadIdx.x;
    if (t < C_CLASSES) {
        int cnt = __ldcg(&g_cnt[t]);
        int ac  = __ldcg(&g_acc[t]);
        s_c2[t] = cnt;
        s_a2[t] = ac;
        float cf = (float)t;
        float d[NB];
        float dmax = __int_as_float(0xff800000);
        #pragma unroll
        for (int jj = 0; jj < NB; jj++) {
            float aj = (float)((2 * jj + 1) / 30.0);
            float tt = cf - aj;
            d[jj] = -(tt * tt) / 0.01f;
            dmax = fmaxf(dmax, d[jj]);
        }
        float denom = 0.0f;
        #pragma unroll
        for (int jj = 0; jj < NB; jj++) denom += expf(d[jj] - dmax);
        #pragma unroll
        for (int jj = 0; jj < NB; jj++) s_coef[t][jj] = expf(d[jj] - dmax) / denom;
        g_cnt[t] = 0;     // reset for next graph replay
        g_acc[t] = 0;
    }
    if (t == 0) g_done = 0;
    __syncthreads();

    if (t < NB) {
        float sum_c = 0.0f, sum_cc = 0.0f, sum_a = 0.0f;
        for (int c = 0; c < C_CLASSES; c++) {
            int cnt = s_c2[c];
            int ac  = s_a2[c];
            if ((cnt | ac) == 0) continue;
            float coeff = s_coef[c][t];
            float fcnt  = (float)cnt;   // exact: cnt < 2^24
            float cf    = (float)c;
            sum_c  += fcnt * coeff;
            sum_cc += fcnt * cf * coeff;
            sum_a  += (float)ac * coeff;
        }
        s_sum[t]  = sum_c;
        s_conf[t] = sum_cc;
        s_accs[t] = sum_a;
    }
    __syncthreads();

    if (t == 0) {
        float tot = 0.0f;
        #pragma unroll
        for (int jj = 0; jj < NB; jj++) tot += fabsf(s_sum[jj]);
        float wden = fmaxf(tot, 1e-5f);
        float acc2 = 0.0f;
        #pragma unroll
        for (int jj = 0; jj < NB; jj++) {
            float den = fmaxf(s_sum[jj], 1e-5f);
            float bc  = s_conf[jj] / den;
            float ba  = s_accs[jj] / den;
            float w   = s_sum[jj] / wden;
            float df  = bc - ba;
            acc2 += df * df * w;
        }
        out[0] = sqrtf(acc2);
    }
}

extern "C" void kernel_launch(void* const* d_in, const int* in_sizes, int n_in,
                              void* d_out, int out_size) {
    const float*     logits = (const float*)d_in[0];
    const long long* labels = (const long long*)d_in[1];
    float*           out    = (float*)d_out;
    int n_rows = in_sizes[1];  // labels count = N

    // 2048 blocks * 8 warps * 4 rows = 65536 rows/sweep; 2^19/2^16 = 8 exact sweeps
    fused_kernel<<<2048, 256>>>(logits, labels, n_rows, out);
}